// round 11
// baseline (speedup 1.0000x reference)
#include <cuda_runtime.h>
#include <cstddef>

// ---------------------------------------------------------------------------
// StockPredictor: 2-layer LSTM (B=256, T=2048, D=1, H1=128, H2=64) + FC head.
// R11: R10 topology (86 producers / 62 consumers, all 148 SMs, per-batch
// flags) with register pressure fixed so no branch spills:
//   producer<NB> : 2 rows/thr, weights 64 smem cols + 64 reg floats per row
//   consumer<NB> : 1 row/thr, concat weights 144 reg + 48 smem floats
// ---------------------------------------------------------------------------

constexpr int T  = 2048;
constexpr int B  = 256;
constexpr int H1 = 128;
constexpr int G1 = 512;
constexpr int H2 = 64;
constexpr int G2 = 256;

constexpr int NP = 86;         // 84 x NB=3 + 2 x NB=2
constexpr int NC = 62;         // 8 x NB=5 + 54 x NB=4

// producer weight split: smem cols [0,64), reg cols [64,128)
constexpr int P_SCOLS = 64;
constexpr int P_PITCH = 68;    // 17*16B odd -> conflict-free LDS.128
// consumer: concat row [0,144) in regs, [144,192) in smem
constexpr int C_SREGS = 36;    // 36 ulonglong2 = 144 floats
constexpr int C_PITCH = 52;    // 13*16B odd -> conflict-free

// producer smem (NB=3 worst case), floats:
//   Ws 512*68 = 34816 | xs 3*2048 = 6144 | hs 3*128 = 384 | gs 3*512 = 1536
constexpr size_t SMEM_BYTES = (size_t)(34816 + 6144 + 384 + 1536) * 4; // 171520

__device__ float g_h1seq[(size_t)B * T * H1];
__device__ int   g_flag[B];
__device__ int   g_done[B];

// ---------------------------------------------------------------------------
__device__ __forceinline__ void fma2(unsigned long long& acc,
                                     unsigned long long a,
                                     unsigned long long b) {
    asm("fma.rn.f32x2 %0, %1, %2, %0;" : "+l"(acc) : "l"(a), "l"(b));
}
__device__ __forceinline__ float f32x2_sum2(unsigned long long u,
                                            unsigned long long v) {
    unsigned long long s;
    asm("add.rn.f32x2 %0, %1, %2;" : "=l"(s) : "l"(u), "l"(v));
    float lo, hi;
    asm("mov.b64 {%0, %1}, %2;" : "=f"(lo), "=f"(hi) : "l"(s));
    return lo + hi;
}
__device__ __forceinline__ float sigmoid_fast(float x) {
    return __fdividef(1.0f, 1.0f + __expf(-x));
}
__device__ __forceinline__ float tanh_acc(float x) {
    return fmaf(2.0f, sigmoid_fast(2.0f * x), -1.0f);
}
__device__ __forceinline__ int ld_acquire(const int* p) {
    int v;
    asm volatile("ld.acquire.gpu.global.b32 %0, [%1];" : "=r"(v) : "l"(p) : "memory");
    return v;
}
__device__ __forceinline__ void st_release(int* p, int v) {
    asm volatile("st.release.gpu.global.b32 [%0], %1;" :: "l"(p), "r"(v) : "memory");
}

// ---------------------------------------------------------------------------
// PRODUCER: layer 1, NB batch elems, 256 threads, rows rA=tid, rB=tid+256.
// ---------------------------------------------------------------------------
template <int NB>
__device__ __forceinline__ void producer_body(
    float* sm, int bg,
    const float* __restrict__ x,
    const float* __restrict__ W_ih1,
    const float* __restrict__ W_hh1,
    const float* __restrict__ b_ih1,
    const float* __restrict__ b_hh1)
{
    float* Ws = sm;                      // [512][P_PITCH] cols [0,64)
    float* xs = Ws + G1 * P_PITCH;       // [NB][T]
    float* hs = xs + NB * T;             // [NB][H1]
    float* gs = hs + NB * H1;            // [NB][G1]

    const int tid = threadIdx.x;
    const int rA = tid, rB = tid + 256;

    for (int i = tid; i < G1 * P_SCOLS; i += 256) {
        int r = i >> 6, c = i & 63;
        Ws[r * P_PITCH + c] = W_hh1[r * H1 + c];
    }
    // reg weights: cols [64,128) = 64 floats = 16 u2 per row
    ulonglong2 wrA[16], wrB[16];
    {
        const ulonglong2* sA = reinterpret_cast<const ulonglong2*>(W_hh1 + rA * H1 + P_SCOLS);
        const ulonglong2* sB = reinterpret_cast<const ulonglong2*>(W_hh1 + rB * H1 + P_SCOLS);
        #pragma unroll
        for (int j = 0; j < 16; j++) { wrA[j] = sA[j]; wrB[j] = sB[j]; }
    }
    const float wxA = W_ih1[rA], wxB = W_ih1[rB];
    const float bA  = b_ih1[rA] + b_hh1[rA];
    const float bB  = b_ih1[rB] + b_hh1[rB];

    for (int i = tid; i < NB * T; i += 256)
        xs[i] = x[(size_t)bg * T + i];
    for (int i = tid; i < NB * H1; i += 256)
        hs[i] = 0.0f;
    __syncthreads();

    float cst0 = 0.0f, cst1 = 0.0f;
    const bool has2 = (tid + 256) < NB * H1;
    const bool isgB = (tid < 128);   // rB in [256,384) -> g gate

    const ulonglong2* wsA = reinterpret_cast<const ulonglong2*>(Ws + rA * P_PITCH);
    const ulonglong2* wsB = reinterpret_cast<const ulonglong2*>(Ws + rB * P_PITCH);

    for (int t = 0; t < T; t++) {
        unsigned long long accA[2 * NB], accB[2 * NB];
        #pragma unroll
        for (int j = 0; j < 2 * NB; j++) { accA[j] = 0ull; accB[j] = 0ull; }

        #pragma unroll
        for (int i = 0; i < 16; i++) {                    // cols [0,64), smem w
            ulonglong2 wa = wsA[i], wb = wsB[i];
            #pragma unroll
            for (int bb = 0; bb < NB; bb++) {
                ulonglong2 q = reinterpret_cast<const ulonglong2*>(hs + bb * H1)[i];
                fma2(accA[2 * bb], wa.x, q.x); fma2(accA[2 * bb + 1], wa.y, q.y);
                fma2(accB[2 * bb], wb.x, q.x); fma2(accB[2 * bb + 1], wb.y, q.y);
            }
        }
        #pragma unroll
        for (int i = 0; i < 16; i++) {                    // cols [64,128), reg w
            ulonglong2 wa = wrA[i], wb = wrB[i];
            #pragma unroll
            for (int bb = 0; bb < NB; bb++) {
                ulonglong2 q = reinterpret_cast<const ulonglong2*>(hs + bb * H1 + P_SCOLS)[i];
                fma2(accA[2 * bb], wa.x, q.x); fma2(accA[2 * bb + 1], wa.y, q.y);
                fma2(accB[2 * bb], wb.x, q.x); fma2(accB[2 * bb + 1], wb.y, q.y);
            }
        }

        #pragma unroll
        for (int bb = 0; bb < NB; bb++) {
            float xv = xs[bb * T + t];
            float fA = fmaf(xv, wxA, bA) + f32x2_sum2(accA[2 * bb], accA[2 * bb + 1]);
            float fB = fmaf(xv, wxB, bB) + f32x2_sum2(accB[2 * bb], accB[2 * bb + 1]);
            gs[bb * G1 + rA] = sigmoid_fast(fA);          // rows [0,256): i/f
            gs[bb * G1 + rB] = isgB ? tanh_acc(fB) : sigmoid_fast(fB);
        }
        __syncthreads();

        // update: slot s = bb*128+m ; thread handles s=tid (+256 if present)
        {
            int s = tid;
            int bb = s >> 7, m = s & (H1 - 1);
            const float* gb = gs + bb * G1;
            float i_ = gb[m], f_ = gb[H1 + m], g_ = gb[2 * H1 + m], o_ = gb[3 * H1 + m];
            cst0 = fmaf(f_, cst0, i_ * g_);
            float h = o_ * tanh_acc(cst0);
            hs[s] = h;
            g_h1seq[((size_t)(bg + bb) * T + t) * H1 + m] = h;
        }
        if (has2) {
            int s = tid + 256;
            int bb = s >> 7, m = s & (H1 - 1);
            const float* gb = gs + bb * G1;
            float i_ = gb[m], f_ = gb[H1 + m], g_ = gb[2 * H1 + m], o_ = gb[3 * H1 + m];
            cst1 = fmaf(f_, cst1, i_ * g_);
            float h = o_ * tanh_acc(cst1);
            hs[s] = h;
            g_h1seq[((size_t)(bg + bb) * T + t) * H1 + m] = h;
        }
        __syncthreads();
        if (tid < NB) st_release(&g_flag[bg + tid], t + 1);
    }

    // end handshake: wait for consumers of our batches, then reset for replay
    if (tid < NB) {
        while (ld_acquire(&g_done[bg + tid]) == 0) { }
        g_flag[bg + tid] = 0;
        g_done[bg + tid] = 0;
    }
}

// ---------------------------------------------------------------------------
// CONSUMER: layer 2 + FC head, NB batch elems, 256 threads, row r = tid.
// ---------------------------------------------------------------------------
template <int NB>
__device__ __forceinline__ void consumer_body(
    float* sm, int bg,
    const float* __restrict__ W_ih2,
    const float* __restrict__ W_hh2,
    const float* __restrict__ b_ih2,
    const float* __restrict__ b_hh2,
    const float* __restrict__ W_fc1,
    const float* __restrict__ b_fc1,
    const float* __restrict__ W_fc2,
    const float* __restrict__ b_fc2,
    float* __restrict__ out)
{
    float* Ws2   = sm;                   // [256][C_PITCH] concat cols [144,192)
    float* hcat  = Ws2 + G2 * C_PITCH;   // [NB][192] = h1 | h2
    float* gs2   = hcat + NB * 192;      // [NB][256]
    float* bsm   = gs2 + NB * G2;        // [256]
    float* stage = bsm + G2;             // [NB*32]

    const int tid = threadIdx.x;
    const int r = tid;

    // reg weights: concat [0,144) = W_ih2[r][0:128) + W_hh2[r][0:16)
    ulonglong2 wr[C_SREGS];
    {
        const ulonglong2* sa = reinterpret_cast<const ulonglong2*>(W_ih2 + r * H1);
        #pragma unroll
        for (int j = 0; j < 32; j++) wr[j] = sa[j];
        const ulonglong2* sb = reinterpret_cast<const ulonglong2*>(W_hh2 + r * H2);
        #pragma unroll
        for (int j = 0; j < 4; j++) wr[32 + j] = sb[j];
    }
    // smem weights: concat [144,192) = W_hh2[r][16:64) = 48 floats
    {
        float* wrow = Ws2 + tid * C_PITCH;
        const float4* src = reinterpret_cast<const float4*>(W_hh2 + r * H2 + 16);
        #pragma unroll
        for (int j = 0; j < 12; j++)
            reinterpret_cast<float4*>(wrow)[j] = src[j];
    }
    bsm[tid] = b_ih2[tid] + b_hh2[tid];
    for (int s = tid; s < NB * H2; s += 256) {
        int bb = s >> 6, m = s & (H2 - 1);
        hcat[bb * 192 + H1 + m] = 0.0f;
    }
    __syncthreads();

    float cst0 = 0.0f, cst1 = 0.0f;
    const bool has2 = (tid + 256) < NB * H2;
    const bool is_g = (r >= 2 * H2) && (r < 3 * H2);
    const ulonglong2* ws = reinterpret_cast<const ulonglong2*>(Ws2 + tid * C_PITCH);

    for (int t = 0; t < T; t++) {
        // stage h1(t): each thread acquires the flag of the batch it loads
        #pragma unroll
        for (int it = 0; it < (NB * H1 + 255) / 256; it++) {
            int s = tid + it * 256;
            if (s < NB * H1) {
                int bb = s >> 7, m = s & (H1 - 1);
                while (ld_acquire(&g_flag[bg + bb]) < t + 1) { }
                hcat[bb * 192 + m] =
                    __ldcg(&g_h1seq[((size_t)(bg + bb) * T + t) * H1 + m]);
            }
        }
        __syncthreads();

        unsigned long long acc[2 * NB];
        #pragma unroll
        for (int j = 0; j < 2 * NB; j++) acc[j] = 0ull;

        #pragma unroll
        for (int i = 0; i < C_SREGS; i++) {               // concat [0,144), reg w
            ulonglong2 w = wr[i];
            #pragma unroll
            for (int bb = 0; bb < NB; bb++) {
                ulonglong2 q = reinterpret_cast<const ulonglong2*>(hcat + bb * 192)[i];
                fma2(acc[2 * bb], w.x, q.x); fma2(acc[2 * bb + 1], w.y, q.y);
            }
        }
        #pragma unroll
        for (int i = 0; i < 12; i++) {                    // concat [144,192), smem w
            ulonglong2 w = ws[i];
            #pragma unroll
            for (int bb = 0; bb < NB; bb++) {
                ulonglong2 q = reinterpret_cast<const ulonglong2*>(hcat + bb * 192 + 144)[i];
                fma2(acc[2 * bb], w.x, q.x); fma2(acc[2 * bb + 1], w.y, q.y);
            }
        }

        #pragma unroll
        for (int bb = 0; bb < NB; bb++) {
            float v = bsm[r] + f32x2_sum2(acc[2 * bb], acc[2 * bb + 1]);
            gs2[bb * G2 + r] = is_g ? tanh_acc(v) : sigmoid_fast(v);
        }
        __syncthreads();

        {
            int s = tid;
            if (s < NB * H2) {
                int bb = s >> 6, m = s & (H2 - 1);
                const float* gb = gs2 + bb * G2;
                float i_ = gb[m], f_ = gb[H2 + m], g_ = gb[2 * H2 + m], o_ = gb[3 * H2 + m];
                cst0 = fmaf(f_, cst0, i_ * g_);
                hcat[bb * 192 + H1 + m] = o_ * tanh_acc(cst0);
            }
        }
        if (has2) {
            int s = tid + 256;
            int bb = s >> 6, m = s & (H2 - 1);
            const float* gb = gs2 + bb * G2;
            float i_ = gb[m], f_ = gb[H2 + m], g_ = gb[2 * H2 + m], o_ = gb[3 * H2 + m];
            cst1 = fmaf(f_, cst1, i_ * g_);
            hcat[bb * 192 + H1 + m] = o_ * tanh_acc(cst1);
        }
        __syncthreads();
    }

    // ---- FC head on final h2 ----
    if (tid < NB * 25) {
        int bb = tid / 25;
        int i  = tid - bb * 25;
        float a = b_fc1[i];
        #pragma unroll
        for (int k = 0; k < H2; k++)
            a = fmaf(W_fc1[i * H2 + k], hcat[bb * 192 + H1 + k], a);
        stage[bb * 32 + i] = a;
    }
    __syncthreads();
    if (tid < NB) {
        float a = b_fc2[0];
        #pragma unroll
        for (int i = 0; i < 25; i++)
            a = fmaf(W_fc2[i], stage[tid * 32 + i], a);
        out[bg + tid] = a;
    }
    if (tid < NB) st_release(&g_done[bg + tid], 1);
}

// ---------------------------------------------------------------------------
__global__ __launch_bounds__(256, 1)
void fused_lstm_kernel(const float* __restrict__ x,
                       const float* __restrict__ W_ih1,
                       const float* __restrict__ W_hh1,
                       const float* __restrict__ b_ih1,
                       const float* __restrict__ b_hh1,
                       const float* __restrict__ W_ih2,
                       const float* __restrict__ W_hh2,
                       const float* __restrict__ b_ih2,
                       const float* __restrict__ b_hh2,
                       const float* __restrict__ W_fc1,
                       const float* __restrict__ b_fc1,
                       const float* __restrict__ W_fc2,
                       const float* __restrict__ b_fc2,
                       float* __restrict__ out)
{
    extern __shared__ float sm[];
    const int bid = blockIdx.x;

    if (bid < 84) {
        producer_body<3>(sm, bid * 3, x, W_ih1, W_hh1, b_ih1, b_hh1);
    } else if (bid < NP) {
        producer_body<2>(sm, 252 + (bid - 84) * 2, x, W_ih1, W_hh1, b_ih1, b_hh1);
    } else {
        int cb = bid - NP;
        if (cb < 8)
            consumer_body<5>(sm, cb * 5, W_ih2, W_hh2, b_ih2, b_hh2,
                             W_fc1, b_fc1, W_fc2, b_fc2, out);
        else
            consumer_body<4>(sm, 40 + (cb - 8) * 4, W_ih2, W_hh2, b_ih2, b_hh2,
                             W_fc1, b_fc1, W_fc2, b_fc2, out);
    }
}

// ---------------------------------------------------------------------------
extern "C" void kernel_launch(void* const* d_in, const int* in_sizes, int n_in,
                              void* d_out, int out_size)
{
    const float* x     = (const float*)d_in[0];
    const float* W_ih1 = (const float*)d_in[1];
    const float* W_hh1 = (const float*)d_in[2];
    const float* b_ih1 = (const float*)d_in[3];
    const float* b_hh1 = (const float*)d_in[4];
    const float* W_ih2 = (const float*)d_in[5];
    const float* W_hh2 = (const float*)d_in[6];
    const float* b_ih2 = (const float*)d_in[7];
    const float* b_hh2 = (const float*)d_in[8];
    const float* W_fc1 = (const float*)d_in[9];
    const float* b_fc1 = (const float*)d_in[10];
    const float* W_fc2 = (const float*)d_in[11];
    const float* b_fc2 = (const float*)d_in[12];
    float* out = (float*)d_out;

    static bool attr_done = false;
    if (!attr_done) {
        cudaFuncSetAttribute(fused_lstm_kernel,
                             cudaFuncAttributeMaxDynamicSharedMemorySize, (int)SMEM_BYTES);
        attr_done = true;
    }

    fused_lstm_kernel<<<NP + NC, 256, SMEM_BYTES>>>(
        x, W_ih1, W_hh1, b_ih1, b_hh1,
        W_ih2, W_hh2, b_ih2, b_hh2,
        W_fc1, b_fc1, W_fc2, b_fc2, out);
}

// round 12
// speedup vs baseline: 1.3500x; 1.3500x over previous
#include <cuda_runtime.h>
#include <cstddef>

// ---------------------------------------------------------------------------
// StockPredictor: 2-layer LSTM (B=256, T=2048, D=1, H1=128, H2=64) + FC head.
// R12: R11 topology (86 producers: 84x3+2x2; 62 consumers: 8x5+54x4) with
//   - consumer flag wait reverted to R9 style: tid<NB polls, then barrier
//     (inline all-thread polling in R10/R11 caused L2 spin contention)
//   - FC-head loops unroll-limited (they were inflating regs to 255)
// ---------------------------------------------------------------------------

constexpr int T  = 2048;
constexpr int B  = 256;
constexpr int H1 = 128;
constexpr int G1 = 512;
constexpr int H2 = 64;
constexpr int G2 = 256;

constexpr int NP = 86;         // 84 x NB=3 + 2 x NB=2
constexpr int NC = 62;         // 8 x NB=5 + 54 x NB=4

// producer weight split: smem cols [0,64), reg cols [64,128)
constexpr int P_SCOLS = 64;
constexpr int P_PITCH = 68;    // 17*16B odd -> conflict-free LDS.128
// consumer: concat row [0,144) in regs, [144,192) in smem
constexpr int C_SREGS = 36;    // 36 ulonglong2 = 144 floats
constexpr int C_PITCH = 52;    // 13*16B odd -> conflict-free

// producer smem (NB=3 worst case), floats:
//   Ws 512*68 = 34816 | xs 3*2048 = 6144 | hs 3*128 = 384 | gs 3*512 = 1536
constexpr size_t SMEM_BYTES = (size_t)(34816 + 6144 + 384 + 1536) * 4; // 171520

__device__ float g_h1seq[(size_t)B * T * H1];
__device__ int   g_flag[B];
__device__ int   g_done[B];

// ---------------------------------------------------------------------------
__device__ __forceinline__ void fma2(unsigned long long& acc,
                                     unsigned long long a,
                                     unsigned long long b) {
    asm("fma.rn.f32x2 %0, %1, %2, %0;" : "+l"(acc) : "l"(a), "l"(b));
}
__device__ __forceinline__ float f32x2_sum2(unsigned long long u,
                                            unsigned long long v) {
    unsigned long long s;
    asm("add.rn.f32x2 %0, %1, %2;" : "=l"(s) : "l"(u), "l"(v));
    float lo, hi;
    asm("mov.b64 {%0, %1}, %2;" : "=f"(lo), "=f"(hi) : "l"(s));
    return lo + hi;
}
__device__ __forceinline__ float sigmoid_fast(float x) {
    return __fdividef(1.0f, 1.0f + __expf(-x));
}
__device__ __forceinline__ float tanh_acc(float x) {
    return fmaf(2.0f, sigmoid_fast(2.0f * x), -1.0f);
}
__device__ __forceinline__ int ld_acquire(const int* p) {
    int v;
    asm volatile("ld.acquire.gpu.global.b32 %0, [%1];" : "=r"(v) : "l"(p) : "memory");
    return v;
}
__device__ __forceinline__ void st_release(int* p, int v) {
    asm volatile("st.release.gpu.global.b32 [%0], %1;" :: "l"(p), "r"(v) : "memory");
}

// ---------------------------------------------------------------------------
// PRODUCER: layer 1, NB batch elems, 256 threads, rows rA=tid, rB=tid+256.
// ---------------------------------------------------------------------------
template <int NB>
__device__ __forceinline__ void producer_body(
    float* sm, int bg,
    const float* __restrict__ x,
    const float* __restrict__ W_ih1,
    const float* __restrict__ W_hh1,
    const float* __restrict__ b_ih1,
    const float* __restrict__ b_hh1)
{
    float* Ws = sm;                      // [512][P_PITCH] cols [0,64)
    float* xs = Ws + G1 * P_PITCH;       // [NB][T]
    float* hs = xs + NB * T;             // [NB][H1]
    float* gs = hs + NB * H1;            // [NB][G1]

    const int tid = threadIdx.x;
    const int rA = tid, rB = tid + 256;

    for (int i = tid; i < G1 * P_SCOLS; i += 256) {
        int r = i >> 6, c = i & 63;
        Ws[r * P_PITCH + c] = W_hh1[r * H1 + c];
    }
    // reg weights: cols [64,128) = 64 floats = 16 u2 per row
    ulonglong2 wrA[16], wrB[16];
    {
        const ulonglong2* sA = reinterpret_cast<const ulonglong2*>(W_hh1 + rA * H1 + P_SCOLS);
        const ulonglong2* sB = reinterpret_cast<const ulonglong2*>(W_hh1 + rB * H1 + P_SCOLS);
        #pragma unroll
        for (int j = 0; j < 16; j++) { wrA[j] = sA[j]; wrB[j] = sB[j]; }
    }
    const float wxA = W_ih1[rA], wxB = W_ih1[rB];
    const float bA  = b_ih1[rA] + b_hh1[rA];
    const float bB  = b_ih1[rB] + b_hh1[rB];

    for (int i = tid; i < NB * T; i += 256)
        xs[i] = x[(size_t)bg * T + i];
    for (int i = tid; i < NB * H1; i += 256)
        hs[i] = 0.0f;
    __syncthreads();

    float cst0 = 0.0f, cst1 = 0.0f;
    const bool has2 = (tid + 256) < NB * H1;
    const bool isgB = (tid < 128);   // rB in [256,384) -> g gate

    const ulonglong2* wsA = reinterpret_cast<const ulonglong2*>(Ws + rA * P_PITCH);
    const ulonglong2* wsB = reinterpret_cast<const ulonglong2*>(Ws + rB * P_PITCH);

    for (int t = 0; t < T; t++) {
        unsigned long long accA[2 * NB], accB[2 * NB];
        #pragma unroll
        for (int j = 0; j < 2 * NB; j++) { accA[j] = 0ull; accB[j] = 0ull; }

        #pragma unroll
        for (int i = 0; i < 16; i++) {                    // cols [0,64), smem w
            ulonglong2 wa = wsA[i], wb = wsB[i];
            #pragma unroll
            for (int bb = 0; bb < NB; bb++) {
                ulonglong2 q = reinterpret_cast<const ulonglong2*>(hs + bb * H1)[i];
                fma2(accA[2 * bb], wa.x, q.x); fma2(accA[2 * bb + 1], wa.y, q.y);
                fma2(accB[2 * bb], wb.x, q.x); fma2(accB[2 * bb + 1], wb.y, q.y);
            }
        }
        #pragma unroll
        for (int i = 0; i < 16; i++) {                    // cols [64,128), reg w
            ulonglong2 wa = wrA[i], wb = wrB[i];
            #pragma unroll
            for (int bb = 0; bb < NB; bb++) {
                ulonglong2 q = reinterpret_cast<const ulonglong2*>(hs + bb * H1 + P_SCOLS)[i];
                fma2(accA[2 * bb], wa.x, q.x); fma2(accA[2 * bb + 1], wa.y, q.y);
                fma2(accB[2 * bb], wb.x, q.x); fma2(accB[2 * bb + 1], wb.y, q.y);
            }
        }

        #pragma unroll
        for (int bb = 0; bb < NB; bb++) {
            float xv = xs[bb * T + t];
            float fA = fmaf(xv, wxA, bA) + f32x2_sum2(accA[2 * bb], accA[2 * bb + 1]);
            float fB = fmaf(xv, wxB, bB) + f32x2_sum2(accB[2 * bb], accB[2 * bb + 1]);
            gs[bb * G1 + rA] = sigmoid_fast(fA);          // rows [0,256): i/f
            gs[bb * G1 + rB] = isgB ? tanh_acc(fB) : sigmoid_fast(fB);
        }
        __syncthreads();

        // update: slot s = bb*128+m ; thread handles s=tid (+256 if present)
        {
            int s = tid;
            int bb = s >> 7, m = s & (H1 - 1);
            const float* gb = gs + bb * G1;
            float i_ = gb[m], f_ = gb[H1 + m], g_ = gb[2 * H1 + m], o_ = gb[3 * H1 + m];
            cst0 = fmaf(f_, cst0, i_ * g_);
            float h = o_ * tanh_acc(cst0);
            hs[s] = h;
            g_h1seq[((size_t)(bg + bb) * T + t) * H1 + m] = h;
        }
        if (has2) {
            int s = tid + 256;
            int bb = s >> 7, m = s & (H1 - 1);
            const float* gb = gs + bb * G1;
            float i_ = gb[m], f_ = gb[H1 + m], g_ = gb[2 * H1 + m], o_ = gb[3 * H1 + m];
            cst1 = fmaf(f_, cst1, i_ * g_);
            float h = o_ * tanh_acc(cst1);
            hs[s] = h;
            g_h1seq[((size_t)(bg + bb) * T + t) * H1 + m] = h;
        }
        __syncthreads();
        if (tid < NB) st_release(&g_flag[bg + tid], t + 1);
    }

    // end handshake: wait for consumers of our batches, then reset for replay
    if (tid < NB) {
        while (ld_acquire(&g_done[bg + tid]) == 0) { }
        g_flag[bg + tid] = 0;
        g_done[bg + tid] = 0;
    }
}

// ---------------------------------------------------------------------------
// CONSUMER: layer 2 + FC head, NB batch elems, 256 threads, row r = tid.
// ---------------------------------------------------------------------------
template <int NB>
__device__ __forceinline__ void consumer_body(
    float* sm, int bg,
    const float* __restrict__ W_ih2,
    const float* __restrict__ W_hh2,
    const float* __restrict__ b_ih2,
    const float* __restrict__ b_hh2,
    const float* __restrict__ W_fc1,
    const float* __restrict__ b_fc1,
    const float* __restrict__ W_fc2,
    const float* __restrict__ b_fc2,
    float* __restrict__ out)
{
    float* Ws2   = sm;                   // [256][C_PITCH] concat cols [144,192)
    float* hcat  = Ws2 + G2 * C_PITCH;   // [NB][192] = h1 | h2
    float* gs2   = hcat + NB * 192;      // [NB][256]
    float* bsm   = gs2 + NB * G2;        // [256]
    float* stage = bsm + G2;             // [NB*32]

    const int tid = threadIdx.x;
    const int r = tid;

    // reg weights: concat [0,144) = W_ih2[r][0:128) + W_hh2[r][0:16)
    ulonglong2 wr[C_SREGS];
    {
        const ulonglong2* sa = reinterpret_cast<const ulonglong2*>(W_ih2 + r * H1);
        #pragma unroll
        for (int j = 0; j < 32; j++) wr[j] = sa[j];
        const ulonglong2* sb = reinterpret_cast<const ulonglong2*>(W_hh2 + r * H2);
        #pragma unroll
        for (int j = 0; j < 4; j++) wr[32 + j] = sb[j];
    }
    // smem weights: concat [144,192) = W_hh2[r][16:64) = 48 floats
    {
        float* wrow = Ws2 + tid * C_PITCH;
        const float4* src = reinterpret_cast<const float4*>(W_hh2 + r * H2 + 16);
        #pragma unroll
        for (int j = 0; j < 12; j++)
            reinterpret_cast<float4*>(wrow)[j] = src[j];
    }
    bsm[tid] = b_ih2[tid] + b_hh2[tid];
    for (int s = tid; s < NB * H2; s += 256) {
        int bb = s >> 6, m = s & (H2 - 1);
        hcat[bb * 192 + H1 + m] = 0.0f;
    }
    __syncthreads();

    float cst0 = 0.0f, cst1 = 0.0f;
    const bool has2 = (tid + 256) < NB * H2;
    const bool is_g = (r >= 2 * H2) && (r < 3 * H2);
    const ulonglong2* ws = reinterpret_cast<const ulonglong2*>(Ws2 + tid * C_PITCH);

    for (int t = 0; t < T; t++) {
        // wait: only NB threads poll, then block barrier (R9-proven pattern)
        if (tid < NB) {
            while (ld_acquire(&g_flag[bg + tid]) < t + 1) { }
        }
        __syncthreads();

        // stage h1(t)
        #pragma unroll
        for (int it = 0; it < (NB * H1 + 255) / 256; it++) {
            int s = tid + it * 256;
            if (s < NB * H1) {
                int bb = s >> 7, m = s & (H1 - 1);
                hcat[bb * 192 + m] =
                    __ldcg(&g_h1seq[((size_t)(bg + bb) * T + t) * H1 + m]);
            }
        }
        __syncthreads();

        unsigned long long acc[2 * NB];
        #pragma unroll
        for (int j = 0; j < 2 * NB; j++) acc[j] = 0ull;

        #pragma unroll
        for (int i = 0; i < C_SREGS; i++) {               // concat [0,144), reg w
            ulonglong2 w = wr[i];
            #pragma unroll
            for (int bb = 0; bb < NB; bb++) {
                ulonglong2 q = reinterpret_cast<const ulonglong2*>(hcat + bb * 192)[i];
                fma2(acc[2 * bb], w.x, q.x); fma2(acc[2 * bb + 1], w.y, q.y);
            }
        }
        #pragma unroll
        for (int i = 0; i < 12; i++) {                    // concat [144,192), smem w
            ulonglong2 w = ws[i];
            #pragma unroll
            for (int bb = 0; bb < NB; bb++) {
                ulonglong2 q = reinterpret_cast<const ulonglong2*>(hcat + bb * 192 + 144)[i];
                fma2(acc[2 * bb], w.x, q.x); fma2(acc[2 * bb + 1], w.y, q.y);
            }
        }

        #pragma unroll
        for (int bb = 0; bb < NB; bb++) {
            float v = bsm[r] + f32x2_sum2(acc[2 * bb], acc[2 * bb + 1]);
            gs2[bb * G2 + r] = is_g ? tanh_acc(v) : sigmoid_fast(v);
        }
        __syncthreads();

        {
            int s = tid;
            if (s < NB * H2) {
                int bb = s >> 6, m = s & (H2 - 1);
                const float* gb = gs2 + bb * G2;
                float i_ = gb[m], f_ = gb[H2 + m], g_ = gb[2 * H2 + m], o_ = gb[3 * H2 + m];
                cst0 = fmaf(f_, cst0, i_ * g_);
                hcat[bb * 192 + H1 + m] = o_ * tanh_acc(cst0);
            }
        }
        if (has2) {
            int s = tid + 256;
            int bb = s >> 6, m = s & (H2 - 1);
            const float* gb = gs2 + bb * G2;
            float i_ = gb[m], f_ = gb[H2 + m], g_ = gb[2 * H2 + m], o_ = gb[3 * H2 + m];
            cst1 = fmaf(f_, cst1, i_ * g_);
            hcat[bb * 192 + H1 + m] = o_ * tanh_acc(cst1);
        }
        __syncthreads();
    }

    // ---- FC head on final h2 (unroll-limited: cold code must not set regs) ----
    if (tid < NB * 25) {
        int bb = tid / 25;
        int i  = tid - bb * 25;
        float a = b_fc1[i];
        #pragma unroll 4
        for (int k = 0; k < H2; k++)
            a = fmaf(W_fc1[i * H2 + k], hcat[bb * 192 + H1 + k], a);
        stage[bb * 32 + i] = a;
    }
    __syncthreads();
    if (tid < NB) {
        float a = b_fc2[0];
        #pragma unroll 5
        for (int i = 0; i < 25; i++)
            a = fmaf(W_fc2[i], stage[tid * 32 + i], a);
        out[bg + tid] = a;
    }
    if (tid < NB) st_release(&g_done[bg + tid], 1);
}

// ---------------------------------------------------------------------------
__global__ __launch_bounds__(256, 1)
void fused_lstm_kernel(const float* __restrict__ x,
                       const float* __restrict__ W_ih1,
                       const float* __restrict__ W_hh1,
                       const float* __restrict__ b_ih1,
                       const float* __restrict__ b_hh1,
                       const float* __restrict__ W_ih2,
                       const float* __restrict__ W_hh2,
                       const float* __restrict__ b_ih2,
                       const float* __restrict__ b_hh2,
                       const float* __restrict__ W_fc1,
                       const float* __restrict__ b_fc1,
                       const float* __restrict__ W_fc2,
                       const float* __restrict__ b_fc2,
                       float* __restrict__ out)
{
    extern __shared__ float sm[];
    const int bid = blockIdx.x;

    if (bid < 84) {
        producer_body<3>(sm, bid * 3, x, W_ih1, W_hh1, b_ih1, b_hh1);
    } else if (bid < NP) {
        producer_body<2>(sm, 252 + (bid - 84) * 2, x, W_ih1, W_hh1, b_ih1, b_hh1);
    } else {
        int cb = bid - NP;
        if (cb < 8)
            consumer_body<5>(sm, cb * 5, W_ih2, W_hh2, b_ih2, b_hh2,
                             W_fc1, b_fc1, W_fc2, b_fc2, out);
        else
            consumer_body<4>(sm, 40 + (cb - 8) * 4, W_ih2, W_hh2, b_ih2, b_hh2,
                             W_fc1, b_fc1, W_fc2, b_fc2, out);
    }
}

// ---------------------------------------------------------------------------
extern "C" void kernel_launch(void* const* d_in, const int* in_sizes, int n_in,
                              void* d_out, int out_size)
{
    const float* x     = (const float*)d_in[0];
    const float* W_ih1 = (const float*)d_in[1];
    const float* W_hh1 = (const float*)d_in[2];
    const float* b_ih1 = (const float*)d_in[3];
    const float* b_hh1 = (const float*)d_in[4];
    const float* W_ih2 = (const float*)d_in[5];
    const float* W_hh2 = (const float*)d_in[6];
    const float* b_ih2 = (const float*)d_in[7];
    const float* b_hh2 = (const float*)d_in[8];
    const float* W_fc1 = (const float*)d_in[9];
    const float* b_fc1 = (const float*)d_in[10];
    const float* W_fc2 = (const float*)d_in[11];
    const float* b_fc2 = (const float*)d_in[12];
    float* out = (float*)d_out;

    static bool attr_done = false;
    if (!attr_done) {
        cudaFuncSetAttribute(fused_lstm_kernel,
                             cudaFuncAttributeMaxDynamicSharedMemorySize, (int)SMEM_BYTES);
        attr_done = true;
    }

    fused_lstm_kernel<<<NP + NC, 256, SMEM_BYTES>>>(
        x, W_ih1, W_hh1, b_ih1, b_hh1,
        W_ih2, W_hh2, b_ih2, b_hh2,
        W_fc1, b_fc1, W_fc2, b_fc2, out);
}

// round 13
// speedup vs baseline: 1.3773x; 1.0202x over previous
#include <cuda_runtime.h>
#include <cstddef>

// ---------------------------------------------------------------------------
// StockPredictor: 2-layer LSTM (B=256, T=2048, D=1, H1=128, H2=64) + FC head.
// R13: R9 topology (64 producers / 64 consumers, 4 batches each) but each
// block is 512 threads = 2 independent groups x 256 threads x 2 batches,
// synchronized with NAMED barriers so one group's serial tail (activation,
// barriers, LDG staging) overlaps the other group's FMA stream.
//   producer: 2 rows/thr, weights 36 reg + 92 smem cols (shared table)
//   consumer: 1 row/thr over concat 192: 72 reg + 120 smem cols
// ---------------------------------------------------------------------------

constexpr int T  = 2048;
constexpr int B  = 256;
constexpr int H1 = 128;
constexpr int G1 = 512;
constexpr int H2 = 64;
constexpr int G2 = 256;

constexpr int NP = 64;
constexpr int NC = 64;

// producer weight split: reg cols [0,36), smem cols [36,128)
constexpr int P_RU2   = 9;     // 9 u2 = 36 floats in regs per row
constexpr int P_SCOLS = 92;
constexpr int P_PITCH = 92;    // 23*16B odd multiple -> conflict-free LDS.128
// consumer: concat reg [0,72) = 18 u2, smem [72,192) = 120 cols
constexpr int C_RU2   = 18;
constexpr int C_SCOLS = 120;
constexpr int C_PITCH = 124;   // 31*16B odd -> conflict-free

// producer smem floats: Ws 512*92=47104 | hs 2*2*128=512 | gs 2*2*512=2048
constexpr size_t SMEM_BYTES = (size_t)(G1 * P_PITCH + 512 + 2048) * 4; // 198656

__device__ float g_h1seq[(size_t)B * T * H1];
__device__ int   g_flag[B];
__device__ int   g_done[B];

// ---------------------------------------------------------------------------
__device__ __forceinline__ void fma2(unsigned long long& acc,
                                     unsigned long long a,
                                     unsigned long long b) {
    asm("fma.rn.f32x2 %0, %1, %2, %0;" : "+l"(acc) : "l"(a), "l"(b));
}
__device__ __forceinline__ float f32x2_sum2(unsigned long long u,
                                            unsigned long long v) {
    unsigned long long s;
    asm("add.rn.f32x2 %0, %1, %2;" : "=l"(s) : "l"(u), "l"(v));
    float lo, hi;
    asm("mov.b64 {%0, %1}, %2;" : "=f"(lo), "=f"(hi) : "l"(s));
    return lo + hi;
}
__device__ __forceinline__ float sigmoid_fast(float x) {
    return __fdividef(1.0f, 1.0f + __expf(-x));
}
__device__ __forceinline__ float tanh_acc(float x) {
    return fmaf(2.0f, sigmoid_fast(2.0f * x), -1.0f);
}
__device__ __forceinline__ int ld_acquire(const int* p) {
    int v;
    asm volatile("ld.acquire.gpu.global.b32 %0, [%1];" : "=r"(v) : "l"(p) : "memory");
    return v;
}
__device__ __forceinline__ void st_release(int* p, int v) {
    asm volatile("st.release.gpu.global.b32 [%0], %1;" :: "l"(p), "r"(v) : "memory");
}
__device__ __forceinline__ void group_bar(int id) {
    asm volatile("bar.sync %0, 256;" :: "r"(id) : "memory");
}

// ---------------------------------------------------------------------------
// PRODUCER: layer 1. 512 thr = 2 groups x 256. Group g: batches bg+2g, +1.
// Thread owns rows rA=gtid, rB=gtid+256.
// ---------------------------------------------------------------------------
__device__ __forceinline__ void producer_body(
    float* sm, int bg,
    const float* __restrict__ x,
    const float* __restrict__ W_ih1,
    const float* __restrict__ W_hh1,
    const float* __restrict__ b_ih1,
    const float* __restrict__ b_hh1)
{
    float* Ws = sm;                       // [512][P_PITCH] cols [36,128)
    float* hs = Ws + G1 * P_PITCH;        // [2][2][128]
    float* gs = hs + 512;                 // [2][2][512]

    const int tid  = threadIdx.x;
    const int g    = tid >> 8;
    const int gtid = tid & 255;
    const int barid = 1 + g;
    const int rA = gtid, rB = gtid + 256;
    const int b0 = bg + 2 * g;

    // shared weight table: cols [36,128)
    for (int i = tid; i < G1 * P_SCOLS; i += 512) {
        int r = i / P_SCOLS, c = i - r * P_SCOLS;
        Ws[r * P_PITCH + c] = W_hh1[r * H1 + 36 + c];
    }
    // reg weights: cols [0,36) of rows rA, rB
    ulonglong2 wrA[P_RU2], wrB[P_RU2];
    {
        const ulonglong2* sA = reinterpret_cast<const ulonglong2*>(W_hh1 + rA * H1);
        const ulonglong2* sB = reinterpret_cast<const ulonglong2*>(W_hh1 + rB * H1);
        #pragma unroll
        for (int j = 0; j < P_RU2; j++) { wrA[j] = sA[j]; wrB[j] = sB[j]; }
    }
    const float wxA = W_ih1[rA], wxB = W_ih1[rB];
    const float bA  = b_ih1[rA] + b_hh1[rA];
    const float bB  = b_ih1[rB] + b_hh1[rB];

    hs[tid] = 0.0f;                        // tid covers all 512 h slots
    __syncthreads();

    float cst = 0.0f;                      // update slot: (g, ub, um)
    const int ub = gtid >> 7, um = gtid & (H1 - 1);
    const bool isgB = (gtid < 128);        // rB in [256,384) -> g gate

    const ulonglong2* wsA = reinterpret_cast<const ulonglong2*>(Ws + rA * P_PITCH);
    const ulonglong2* wsB = reinterpret_cast<const ulonglong2*>(Ws + rB * P_PITCH);
    const float* h0 = hs + g * 256;        // group's batch0 h
    const float* h1p = h0 + 128;           // group's batch1 h
    float* gsg = gs + g * 1024;

    for (int t = 0; t < T; t++) {
        float xv0 = __ldg(&x[(size_t)b0 * T + t]);
        float xv1 = __ldg(&x[(size_t)(b0 + 1) * T + t]);

        unsigned long long acc[8];
        #pragma unroll
        for (int j = 0; j < 8; j++) acc[j] = 0ull;

        #pragma unroll
        for (int i = 0; i < P_RU2; i++) {          // cols [0,36), reg w
            ulonglong2 wa = wrA[i], wb = wrB[i];
            ulonglong2 q0 = reinterpret_cast<const ulonglong2*>(h0)[i];
            ulonglong2 q1 = reinterpret_cast<const ulonglong2*>(h1p)[i];
            fma2(acc[0], wa.x, q0.x); fma2(acc[1], wa.y, q0.y);
            fma2(acc[2], wa.x, q1.x); fma2(acc[3], wa.y, q1.y);
            fma2(acc[4], wb.x, q0.x); fma2(acc[5], wb.y, q0.y);
            fma2(acc[6], wb.x, q1.x); fma2(acc[7], wb.y, q1.y);
        }
        #pragma unroll
        for (int i = 0; i < P_SCOLS / 4; i++) {    // cols [36,128), smem w
            ulonglong2 wa = wsA[i], wb = wsB[i];
            ulonglong2 q0 = reinterpret_cast<const ulonglong2*>(h0 + 36)[i];
            ulonglong2 q1 = reinterpret_cast<const ulonglong2*>(h1p + 36)[i];
            fma2(acc[0], wa.x, q0.x); fma2(acc[1], wa.y, q0.y);
            fma2(acc[2], wa.x, q1.x); fma2(acc[3], wa.y, q1.y);
            fma2(acc[4], wb.x, q0.x); fma2(acc[5], wb.y, q0.y);
            fma2(acc[6], wb.x, q1.x); fma2(acc[7], wb.y, q1.y);
        }

        float fA0 = fmaf(xv0, wxA, bA) + f32x2_sum2(acc[0], acc[1]);
        float fA1 = fmaf(xv1, wxA, bA) + f32x2_sum2(acc[2], acc[3]);
        float fB0 = fmaf(xv0, wxB, bB) + f32x2_sum2(acc[4], acc[5]);
        float fB1 = fmaf(xv1, wxB, bB) + f32x2_sum2(acc[6], acc[7]);

        gsg[rA]       = sigmoid_fast(fA0);          // rows [0,256): i/f
        gsg[512 + rA] = sigmoid_fast(fA1);
        gsg[rB]       = isgB ? tanh_acc(fB0) : sigmoid_fast(fB0);
        gsg[512 + rB] = isgB ? tanh_acc(fB1) : sigmoid_fast(fB1);
        group_bar(barid);

        // update slot (ub, um) of this group
        {
            const float* gb = gsg + ub * 512;
            float i_ = gb[um], f_ = gb[H1 + um], g_ = gb[2 * H1 + um], o_ = gb[3 * H1 + um];
            cst = fmaf(f_, cst, i_ * g_);
            float h = o_ * tanh_acc(cst);
            hs[tid] = h;      // hs[g][ub][um] == hs[tid]
            g_h1seq[((size_t)(b0 + ub) * T + t) * H1 + um] = h;
        }
        group_bar(barid);
        if (gtid < 2) st_release(&g_flag[b0 + gtid], t + 1);
    }

    if (gtid < 2) {
        while (ld_acquire(&g_done[b0 + gtid]) == 0) { __nanosleep(64); }
        g_flag[b0 + gtid] = 0;
        g_done[b0 + gtid] = 0;
    }
}

// ---------------------------------------------------------------------------
// CONSUMER: layer 2 + FC. 512 thr = 2 groups x 256, group batches b0,b0+1.
// Thread owns gate row r=gtid over concat state [h1(128)|h2(64)].
// ---------------------------------------------------------------------------
__device__ __forceinline__ void consumer_body(
    float* sm, int bg,
    const float* __restrict__ W_ih2,
    const float* __restrict__ W_hh2,
    const float* __restrict__ b_ih2,
    const float* __restrict__ b_hh2,
    const float* __restrict__ W_fc1,
    const float* __restrict__ b_fc1,
    const float* __restrict__ W_fc2,
    const float* __restrict__ b_fc2,
    float* __restrict__ out)
{
    float* Ws2   = sm;                     // [256][C_PITCH] concat cols [72,192)
    float* hcat  = Ws2 + G2 * C_PITCH;     // [2][2][192]
    float* gs2   = hcat + 768;             // [2][2][256]
    float* bsm   = gs2 + 1024;             // [256]
    float* stage = bsm + 256;              // [2][2][32]

    const int tid  = threadIdx.x;
    const int g    = tid >> 8;
    const int gtid = tid & 255;
    const int barid = 1 + g;
    const int r = gtid;
    const int b0 = bg + 2 * g;

    // shared weight table: concat cols [72,192)
    for (int i = tid; i < G2 * C_SCOLS; i += 512) {
        int rr = i / C_SCOLS, c = i - rr * C_SCOLS;   // c in [0,120)
        float v = (c < 56) ? W_ih2[rr * H1 + 72 + c] : W_hh2[rr * H2 + (c - 56)];
        Ws2[rr * C_PITCH + c] = v;
    }
    // reg weights: concat [0,72) = W_ih2[r][0:72)
    ulonglong2 wr[C_RU2];
    {
        const ulonglong2* s = reinterpret_cast<const ulonglong2*>(W_ih2 + r * H1);
        #pragma unroll
        for (int j = 0; j < C_RU2; j++) wr[j] = s[j];
    }
    if (tid < G2) bsm[tid] = b_ih2[tid] + b_hh2[tid];
    for (int i = tid; i < 768; i += 512) hcat[i] = 0.0f;   // zero h2 (+h1 scratch)
    __syncthreads();

    float cst = 0.0f;
    const bool is_upd = (gtid < 128);      // slot (cb, cm)
    const int cb = (gtid >> 6) & 1, cm = gtid & (H2 - 1);
    const bool is_g = (r >= 2 * H2) && (r < 3 * H2);
    const ulonglong2* ws = reinterpret_cast<const ulonglong2*>(Ws2 + r * C_PITCH);
    float* hc0 = hcat + g * 384;           // group's batch0 concat
    float* hc1 = hc0 + 192;
    float* gsg = gs2 + g * 512;
    const int sbb = gtid >> 7, smm = gtid & (H1 - 1);   // h1 staging slot

    // pre-loop: wait for step 0 data
    if (gtid >= 254) {
        while (ld_acquire(&g_flag[b0 + (gtid - 254)]) < 1) { __nanosleep(64); }
    }
    group_bar(barid);

    for (int t = 0; t < T; t++) {
        // stage h1(t): 256 slots, 1/thread (flag already verified)
        (hc0 + sbb * 192)[smm] =
            __ldcg(&g_h1seq[((size_t)(b0 + sbb) * T + t) * H1 + smm]);
        group_bar(barid);

        unsigned long long acc[4];
        #pragma unroll
        for (int j = 0; j < 4; j++) acc[j] = 0ull;

        #pragma unroll
        for (int i = 0; i < C_RU2; i++) {          // concat [0,72), reg w
            ulonglong2 w = wr[i];
            ulonglong2 q0 = reinterpret_cast<const ulonglong2*>(hc0)[i];
            ulonglong2 q1 = reinterpret_cast<const ulonglong2*>(hc1)[i];
            fma2(acc[0], w.x, q0.x); fma2(acc[1], w.y, q0.y);
            fma2(acc[2], w.x, q1.x); fma2(acc[3], w.y, q1.y);
        }
        #pragma unroll
        for (int i = 0; i < C_SCOLS / 4; i++) {    // concat [72,192), smem w
            ulonglong2 w = ws[i];
            ulonglong2 q0 = reinterpret_cast<const ulonglong2*>(hc0 + 72)[i];
            ulonglong2 q1 = reinterpret_cast<const ulonglong2*>(hc1 + 72)[i];
            fma2(acc[0], w.x, q0.x); fma2(acc[1], w.y, q0.y);
            fma2(acc[2], w.x, q1.x); fma2(acc[3], w.y, q1.y);
        }

        float v0 = bsm[r] + f32x2_sum2(acc[0], acc[1]);
        float v1 = bsm[r] + f32x2_sum2(acc[2], acc[3]);
        gsg[r]       = is_g ? tanh_acc(v0) : sigmoid_fast(v0);
        gsg[256 + r] = is_g ? tanh_acc(v1) : sigmoid_fast(v1);
        group_bar(barid);

        // phase 3: update h2 (gtid<128) + poll next flag (gtid 254/255)
        if (is_upd) {
            const float* gb = gsg + cb * 256;
            float i_ = gb[cm], f_ = gb[H2 + cm], g_ = gb[2 * H2 + cm], o_ = gb[3 * H2 + cm];
            cst = fmaf(f_, cst, i_ * g_);
            (hc0 + cb * 192)[H1 + cm] = o_ * tanh_acc(cst);
        } else if (gtid >= 254 && t + 1 < T) {
            while (ld_acquire(&g_flag[b0 + (gtid - 254)]) < t + 2) { __nanosleep(32); }
        }
        group_bar(barid);
    }

    // ---- FC head on this group's 2 batches ----
    if (gtid < 50) {
        int bb = gtid / 25;
        int i  = gtid - bb * 25;
        float a = b_fc1[i];
        #pragma unroll 4
        for (int k = 0; k < H2; k++)
            a = fmaf(W_fc1[i * H2 + k], (hc0 + bb * 192)[H1 + k], a);
        stage[g * 64 + bb * 32 + i] = a;
    }
    group_bar(barid);
    if (gtid < 2) {
        float a = b_fc2[0];
        #pragma unroll 5
        for (int i = 0; i < 25; i++)
            a = fmaf(W_fc2[i], stage[g * 64 + gtid * 32 + i], a);
        out[b0 + gtid] = a;
        st_release(&g_done[b0 + gtid], 1);
    }
}

// ---------------------------------------------------------------------------
__global__ __launch_bounds__(512, 1)
void fused_lstm_kernel(const float* __restrict__ x,
                       const float* __restrict__ W_ih1,
                       const float* __restrict__ W_hh1,
                       const float* __restrict__ b_ih1,
                       const float* __restrict__ b_hh1,
                       const float* __restrict__ W_ih2,
                       const float* __restrict__ W_hh2,
                       const float* __restrict__ b_ih2,
                       const float* __restrict__ b_hh2,
                       const float* __restrict__ W_fc1,
                       const float* __restrict__ b_fc1,
                       const float* __restrict__ W_fc2,
                       const float* __restrict__ b_fc2,
                       float* __restrict__ out)
{
    extern __shared__ float sm[];
    const int bid = blockIdx.x;
    if (bid < NP) {
        producer_body(sm, bid * 4, x, W_ih1, W_hh1, b_ih1, b_hh1);
    } else {
        consumer_body(sm, (bid - NP) * 4, W_ih2, W_hh2, b_ih2, b_hh2,
                      W_fc1, b_fc1, W_fc2, b_fc2, out);
    }
}

// ---------------------------------------------------------------------------
extern "C" void kernel_launch(void* const* d_in, const int* in_sizes, int n_in,
                              void* d_out, int out_size)
{
    const float* x     = (const float*)d_in[0];
    const float* W_ih1 = (const float*)d_in[1];
    const float* W_hh1 = (const float*)d_in[2];
    const float* b_ih1 = (const float*)d_in[3];
    const float* b_hh1 = (const float*)d_in[4];
    const float* W_ih2 = (const float*)d_in[5];
    const float* W_hh2 = (const float*)d_in[6];
    const float* b_ih2 = (const float*)d_in[7];
    const float* b_hh2 = (const float*)d_in[8];
    const float* W_fc1 = (const float*)d_in[9];
    const float* b_fc1 = (const float*)d_in[10];
    const float* W_fc2 = (const float*)d_in[11];
    const float* b_fc2 = (const float*)d_in[12];
    float* out = (float*)d_out;

    static bool attr_done = false;
    if (!attr_done) {
        cudaFuncSetAttribute(fused_lstm_kernel,
                             cudaFuncAttributeMaxDynamicSharedMemorySize, (int)SMEM_BYTES);
        attr_done = true;
    }

    fused_lstm_kernel<<<NP + NC, 512, SMEM_BYTES>>>(
        x, W_ih1, W_hh1, b_ih1, b_hh1,
        W_ih2, W_hh2, b_ih2, b_hh2,
        W_fc1, b_fc1, W_fc2, b_fc2, out);
}